// round 10
// baseline (speedup 1.0000x reference)
#include <cuda_runtime.h>
#include <cuda_fp16.h>
#include <cstdint>

#define N_NODES 50000
#define N_EDGES 800000
#define DIM 128
#define LN_EPS 1e-5f
#define SCAN_B 196          // ceil(50000/256)
#define WTILE 16384         // floats per 128x128 weight

// ---------------- scratch: __device__ globals, device-side references only --
__device__ int    g_is64;
__device__ int    g_deg[N_NODES];
__device__ int    g_rowptr[N_NODES + 1];
__device__ int    g_cursor[N_NODES];
__device__ int    g_colsrc[N_EDGES];
__device__ int    g_bsum[256];
__device__ float4 g_X4[(size_t)N_NODES * 32];      // tf32-rounded input x
__device__ float4 g_W4[4 * WTILE / 4];             // tf32-rounded weights
__device__ __half g_P16[(size_t)N_NODES * DIM];    // mean branch (pre-agg), fp16
__device__ float4 g_Q4[(size_t)N_NODES * 32];      // self branch, fp32
__device__ float4 g_h14[(size_t)N_NODES * 32];     // layer-1 output (tf32-rounded)

__device__ __forceinline__ float to_tf32(float v) {
    uint32_t u;
    asm("cvt.rna.tf32.f32 %0, %1;" : "=r"(u) : "f"(v));
    return __uint_as_float(u);
}

// ---------------- setup: zero deg + dtype probe + tf32 pre-round ------------
__global__ void k_setup(const float* __restrict__ x,
                        const float* __restrict__ W1l, const float* __restrict__ W1r,
                        const float* __restrict__ W2l, const float* __restrict__ W2r,
                        const int* __restrict__ ei32) {
    int i = blockIdx.x * blockDim.x + threadIdx.x;
    if (i < N_NODES * DIM) ((float*)g_X4)[i] = to_tf32(x[i]);
    if (i < WTILE) {
        float* W = (float*)g_W4;
        W[i]             = to_tf32(W1l[i]);
        W[WTILE + i]     = to_tf32(W1r[i]);
        W[2 * WTILE + i] = to_tf32(W2l[i]);
        W[3 * WTILE + i] = to_tf32(W2r[i]);
    }
    if (i < N_NODES) g_deg[i] = 0;
    if (i == 0) {
        int allzero = 1;
        for (int k = 0; k < 64; k++)
            if (ei32[2 * k + 1] != 0) { allzero = 0; break; }
        g_is64 = allzero;
    }
}

__device__ __forceinline__ int edge_at(const void* __restrict__ ei, int pos) {
    if (g_is64) return (int)((const long long*)ei)[pos];
    return ((const int*)ei)[pos];
}

// ---------------- CSR build ----------------
__global__ void k_hist(const void* __restrict__ ei) {
    int e = blockIdx.x * blockDim.x + threadIdx.x;
    if (e < N_EDGES) {
        int d = edge_at(ei, N_EDGES + e);
        if (d >= 0 && d < N_NODES) atomicAdd(&g_deg[d], 1);
    }
}

__global__ void k_scan1() {
    __shared__ int sm[256];
    int t = threadIdx.x;
    int i = blockIdx.x * 256 + t;
    sm[t] = (i < N_NODES) ? g_deg[i] : 0;
    __syncthreads();
#pragma unroll
    for (int off = 128; off > 0; off >>= 1) {
        if (t < off) sm[t] += sm[t + off];
        __syncthreads();
    }
    if (t == 0) g_bsum[blockIdx.x] = sm[0];
}

__global__ void k_scan2() {
    __shared__ int sm[256];
    int t = threadIdx.x;
    int v = (t < SCAN_B) ? g_bsum[t] : 0;
    sm[t] = v;
    __syncthreads();
#pragma unroll
    for (int off = 1; off < 256; off <<= 1) {
        int u = (t >= off) ? sm[t - off] : 0;
        __syncthreads();
        sm[t] += u;
        __syncthreads();
    }
    if (t < SCAN_B) g_bsum[t] = sm[t] - v;
}

__global__ void k_scan3() {
    __shared__ int sm[256];
    int t = threadIdx.x;
    int i = blockIdx.x * 256 + t;
    int v = (i < N_NODES) ? g_deg[i] : 0;
    sm[t] = v;
    __syncthreads();
#pragma unroll
    for (int off = 1; off < 256; off <<= 1) {
        int u = (t >= off) ? sm[t - off] : 0;
        __syncthreads();
        sm[t] += u;
        __syncthreads();
    }
    int excl = sm[t] - v + g_bsum[blockIdx.x];
    if (i < N_NODES) { g_rowptr[i] = excl; g_cursor[i] = excl; }
    if (i == N_NODES - 1) g_rowptr[N_NODES] = excl + v;
}

__global__ void k_fill(const void* __restrict__ ei) {
    int e = blockIdx.x * blockDim.x + threadIdx.x;
    if (e < N_EDGES) {
        int d = edge_at(ei, N_EDGES + e);
        if (d >= 0 && d < N_NODES) {
            int s = edge_at(ei, e);
            if (s < 0) s = 0;
            if (s >= N_NODES) s = N_NODES - 1;
            int pos = atomicAdd(&g_cursor[d], 1);
            g_colsrc[pos] = s;
        }
    }
}

// ---------------- merged tf32 GEMM: P16 = A@Wp^T (fp16), Q = A@Wq^T (fp32) --
// Both weights resident in smem (XOR-swizzled, stride 32); A 2-stage cp.async.
__device__ __forceinline__ void mma_tf32(float c[4], const uint32_t a[4],
                                         const uint32_t b[2]) {
    asm volatile(
        "mma.sync.aligned.m16n8k8.row.col.f32.tf32.tf32.f32 "
        "{%0,%1,%2,%3}, {%4,%5,%6,%7}, {%8,%9}, {%0,%1,%2,%3};\n"
        : "+f"(c[0]), "+f"(c[1]), "+f"(c[2]), "+f"(c[3])
        : "r"(a[0]), "r"(a[1]), "r"(a[2]), "r"(a[3]),
          "r"(b[0]), "r"(b[1]));
}

__device__ __forceinline__ void cp_async16(float* smem_dst, const float* gsrc, bool valid) {
    uint32_t s = (uint32_t)__cvta_generic_to_shared(smem_dst);
    int sz = valid ? 16 : 0;
    asm volatile("cp.async.ca.shared.global [%0], [%1], 16, %2;\n"
                 :: "r"(s), "l"(gsrc), "r"(sz));
}
#define CP_COMMIT() asm volatile("cp.async.commit_group;\n")
#define CP_WAIT1()  asm volatile("cp.async.wait_group 1;\n")
#define CP_WAIT0()  asm volatile("cp.async.wait_group 0;\n")

// dyn smem layout: Ws[2*WTILE] (swizzled), As[2][128*32] (swizzled)
#define GEMM_SMEM_BYTES ((2 * WTILE + 2 * 4096) * 4)

__global__ __launch_bounds__(256, 1) void k_gemm2(int layer1, int wP, int wQ) {
    extern __shared__ float dynsm[];
    float* Ws = dynsm;
    float* As = dynsm + 2 * WTILE;

    const float* A = layer1 ? (const float*)g_X4 : (const float*)g_h14;
    int tid = threadIdx.x;
    int r0 = blockIdx.x * 128;

    // fill both weights into swizzled smem (float4, 32 iters/thread)
    {
        const float4* WPp = g_W4 + (size_t)wP * (WTILE / 4);
        const float4* WQp = g_W4 + (size_t)wQ * (WTILE / 4);
        for (int i = tid; i < WTILE / 4; i += 256) {
            int n = i >> 5;               // 32 float4 per 128-float row
            int kv = (i & 31) * 4;
            int sw = n * 128 + (kv ^ ((n & 7) << 2));
            *(float4*)&Ws[sw] = WPp[i];
            *(float4*)&Ws[WTILE + sw] = WQp[i];
        }
    }

    // prefetch A stage 0 (kt = 0)
    {
        float* dst = As;
#pragma unroll
        for (int i = 0; i < 4; i++) {
            int linear = i * 256 + tid;
            int m = linear >> 3;
            int kv = (linear & 7) * 4;
            int row = r0 + m;
            cp_async16(&dst[m * 32 + (kv ^ ((m & 7) << 2))],
                       A + (size_t)row * DIM + kv, row < N_NODES);
        }
        CP_COMMIT();
    }

    int wid = tid >> 5, lane = tid & 31;
    int g = lane >> 2, tg = lane & 3;
    int warp_m = (wid >> 1) * 32;
    int warp_n = (wid & 1) * 64;

    float accP[2][8][4], accQ[2][8][4];
#pragma unroll
    for (int mt = 0; mt < 2; mt++)
#pragma unroll
        for (int nt = 0; nt < 8; nt++)
#pragma unroll
            for (int q = 0; q < 4; q++) { accP[mt][nt][q] = 0.f; accQ[mt][nt][q] = 0.f; }

    __syncthreads();   // weights visible to all warps

#pragma unroll 1
    for (int kt = 0; kt < 4; kt++) {
        if (kt < 3) {
            // prefetch next stage, then wait for current
            float* dst = As + ((kt + 1) & 1) * 4096;
            int ka = (kt + 1) * 32;
#pragma unroll
            for (int i = 0; i < 4; i++) {
                int linear = i * 256 + tid;
                int m = linear >> 3;
                int kv = (linear & 7) * 4;
                int row = r0 + m;
                cp_async16(&dst[m * 32 + (kv ^ ((m & 7) << 2))],
                           A + (size_t)row * DIM + ka + kv, row < N_NODES);
            }
            CP_COMMIT();
            CP_WAIT1();
        } else {
            CP_WAIT0();
        }
        __syncthreads();

        const float* Ac = As + (kt & 1) * 4096;
        int kg0 = kt * 32;
#pragma unroll
        for (int ks = 0; ks < 32; ks += 8) {
            int kc = ks + tg;
            uint32_t afr[2][4];
#pragma unroll
            for (int mt = 0; mt < 2; mt++) {
                int rm = warp_m + mt * 16 + g;
                int xo = (rm & 7) << 2;
                const float* Ar = Ac + rm * 32;
                afr[mt][0] = __float_as_uint(Ar[kc ^ xo]);
                afr[mt][1] = __float_as_uint(Ar[256 + (kc ^ xo)]);
                afr[mt][2] = __float_as_uint(Ar[(kc + 4) ^ xo]);
                afr[mt][3] = __float_as_uint(Ar[256 + ((kc + 4) ^ xo)]);
            }
#pragma unroll
            for (int nt = 0; nt < 8; nt++) {
                int cn = warp_n + nt * 8 + g;
                int kk = (kg0 + kc) ^ ((cn & 7) << 2);
                const float* Wr0 = Ws + cn * 128;
                uint32_t bP[2] = { __float_as_uint(Wr0[kk]),
                                   __float_as_uint(Wr0[kk ^ 4]) };
                const float* Wr1 = Wr0 + WTILE;
                uint32_t bQ[2] = { __float_as_uint(Wr1[kk]),
                                   __float_as_uint(Wr1[kk ^ 4]) };
                mma_tf32(accP[0][nt], afr[0], bP);
                mma_tf32(accP[1][nt], afr[1], bP);
                mma_tf32(accQ[0][nt], afr[0], bQ);
                mma_tf32(accQ[1][nt], afr[1], bQ);
            }
        }
        __syncthreads();
    }

    // epilogue: c0:(g,2tg) c1:(g,2tg+1) c2:(g+8,2tg) c3:(g+8,2tg+1)
    float* Q = (float*)g_Q4;
#pragma unroll
    for (int mt = 0; mt < 2; mt++) {
        int row0 = r0 + warp_m + mt * 16 + g;
#pragma unroll
        for (int nt = 0; nt < 8; nt++) {
            int col = warp_n + nt * 8 + tg * 2;
            if (row0 < N_NODES) {
                *(__half2*)(g_P16 + (size_t)row0 * DIM + col) =
                    __floats2half2_rn(accP[mt][nt][0], accP[mt][nt][1]);
                *(float2*)(Q + (size_t)row0 * DIM + col) =
                    make_float2(accQ[mt][nt][0], accQ[mt][nt][1]);
            }
            if (row0 + 8 < N_NODES) {
                *(__half2*)(g_P16 + (size_t)(row0 + 8) * DIM + col) =
                    __floats2half2_rn(accP[mt][nt][2], accP[mt][nt][3]);
                *(float2*)(Q + (size_t)(row0 + 8) * DIM + col) =
                    make_float2(accQ[mt][nt][2], accQ[mt][nt][3]);
            }
        }
    }
}

// ---------------- combine: out = [LN]( relu( mean_gather(P16) + Q + bias ) ) -
// warp per node; indices fetched once per 32-chunk and shfl-broadcast; MLP=8.
#define GATHER1(sidx)                                                          \
    {                                                                          \
        uint2 u = *(const uint2*)(g_P16 + (size_t)(sidx) * DIM + lane * 4);    \
        float2 fa = __half22float2(*(__half2*)&u.x);                           \
        float2 fb = __half22float2(*(__half2*)&u.y);                           \
        ax += fa.x; ay += fa.y; az += fb.x; aw += fb.y;                        \
    }

__global__ void k_combine(const float* __restrict__ bias,
                          const float* __restrict__ lnw,
                          const float* __restrict__ lnb,
                          float* __restrict__ out_ext, int do_ln)
{
    int w = (blockIdx.x * blockDim.x + threadIdx.x) >> 5;
    int lane = threadIdx.x & 31;
    if (w >= N_NODES) return;
    int beg = g_rowptr[w];
    int end = g_rowptr[w + 1];

    float ax = 0.f, ay = 0.f, az = 0.f, aw = 0.f;
    for (int base = beg; base < end; base += 32) {
        int rem = end - base;
        if (rem > 32) rem = 32;
        int idx = g_colsrc[base + (lane < rem ? lane : 0)];
        int j = 0;
        for (; j + 8 <= rem; j += 8) {
            int s0 = __shfl_sync(0xFFFFFFFFu, idx, j);
            int s1 = __shfl_sync(0xFFFFFFFFu, idx, j + 1);
            int s2 = __shfl_sync(0xFFFFFFFFu, idx, j + 2);
            int s3 = __shfl_sync(0xFFFFFFFFu, idx, j + 3);
            int s4 = __shfl_sync(0xFFFFFFFFu, idx, j + 4);
            int s5 = __shfl_sync(0xFFFFFFFFu, idx, j + 5);
            int s6 = __shfl_sync(0xFFFFFFFFu, idx, j + 6);
            int s7 = __shfl_sync(0xFFFFFFFFu, idx, j + 7);
            GATHER1(s0) GATHER1(s1) GATHER1(s2) GATHER1(s3)
            GATHER1(s4) GATHER1(s5) GATHER1(s6) GATHER1(s7)
        }
        for (; j + 4 <= rem; j += 4) {
            int s0 = __shfl_sync(0xFFFFFFFFu, idx, j);
            int s1 = __shfl_sync(0xFFFFFFFFu, idx, j + 1);
            int s2 = __shfl_sync(0xFFFFFFFFu, idx, j + 2);
            int s3 = __shfl_sync(0xFFFFFFFFu, idx, j + 3);
            GATHER1(s0) GATHER1(s1) GATHER1(s2) GATHER1(s3)
        }
        for (; j < rem; j++) {
            int s = __shfl_sync(0xFFFFFFFFu, idx, j);
            GATHER1(s)
        }
    }
    int cnt = end - beg;
    float inv = 1.f / (float)(cnt > 0 ? cnt : 1);

    float4 q = g_Q4[(size_t)w * 32 + lane];
    float4 b4 = ((const float4*)bias)[lane];
    float vx = fmaxf(ax * inv + q.x + b4.x, 0.f);
    float vy = fmaxf(ay * inv + q.y + b4.y, 0.f);
    float vz = fmaxf(az * inv + q.z + b4.z, 0.f);
    float vw = fmaxf(aw * inv + q.w + b4.w, 0.f);

    if (!do_ln) {
        // layer-1 output feeds next GEMM: store tf32-pre-rounded
        g_h14[(size_t)w * 32 + lane] =
            make_float4(to_tf32(vx), to_tf32(vy), to_tf32(vz), to_tf32(vw));
        return;
    }
    // fused LayerNorm across the warp (row = 128 values)
    float s = (vx + vy) + (vz + vw);
#pragma unroll
    for (int off = 16; off > 0; off >>= 1)
        s += __shfl_xor_sync(0xFFFFFFFFu, s, off);
    float mu = s * (1.f / 128.f);
    float dx = vx - mu, dy = vy - mu, dz = vz - mu, dw = vw - mu;
    float sq = (dx * dx + dy * dy) + (dz * dz + dw * dw);
#pragma unroll
    for (int off = 16; off > 0; off >>= 1)
        sq += __shfl_xor_sync(0xFFFFFFFFu, sq, off);
    float rs = rsqrtf(sq * (1.f / 128.f) + LN_EPS);
    float4 wv = ((const float4*)lnw)[lane];
    float4 bv = ((const float4*)lnb)[lane];
    float4 o;
    o.x = dx * rs * wv.x + bv.x;
    o.y = dy * rs * wv.y + bv.y;
    o.z = dz * rs * wv.z + bv.z;
    o.w = dw * rs * wv.w + bv.w;
    ((float4*)out_ext)[(size_t)w * 32 + lane] = o;
}

// ---------------- launch ----------------
extern "C" void kernel_launch(void* const* d_in, const int* in_sizes, int n_in,
                              void* d_out, int out_size) {
    const float* x   = (const float*)d_in[0];
    const void*  ei  = d_in[1];
    const float* W1l = (const float*)d_in[2];
    const float* b1l = (const float*)d_in[3];
    const float* W1r = (const float*)d_in[4];
    const float* W2l = (const float*)d_in[5];
    const float* b2l = (const float*)d_in[6];
    const float* W2r = (const float*)d_in[7];
    const float* lnw = (const float*)d_in[8];
    const float* lnb = (const float*)d_in[9];
    float* out = (float*)d_out;

    const int TB = 256;
    int gridS  = (N_NODES * DIM + TB - 1) / TB;  // 25000 (setup: x rounding)
    int gridE  = (N_EDGES + TB - 1) / TB;
    int gridWN = (N_NODES * 32 + TB - 1) / TB;
    int gridG  = (N_NODES + 127) / 128;          // 391

    // raise dynamic smem limit for the GEMM (idempotent; host-side, not captured)
    cudaFuncSetAttribute(k_gemm2, cudaFuncAttributeMaxDynamicSharedMemorySize,
                         GEMM_SMEM_BYTES);

    // setup (zero deg + probe + tf32 pre-round) + CSR build
    k_setup<<<gridS, TB>>>(x, W1l, W1r, W2l, W2r, (const int*)ei);
    k_hist<<<gridE, TB>>>(ei);
    k_scan1<<<SCAN_B, 256>>>();
    k_scan2<<<1, 256>>>();
    k_scan3<<<SCAN_B, 256>>>();
    k_fill<<<gridE, TB>>>(ei);

    // layer 1: P16 = x@W1l^T, Q = x@W1r^T ; combine -> g_h14
    k_gemm2<<<gridG, TB, GEMM_SMEM_BYTES>>>(1, 0, 1);
    k_combine<<<gridWN, TB>>>(b1l, lnw, lnb, out, 0);

    // layer 2: P16 = h1@W2l^T, Q = h1@W2r^T ; combine+LN -> out
    k_gemm2<<<gridG, TB, GEMM_SMEM_BYTES>>>(0, 2, 3);
    k_combine<<<gridWN, TB>>>(b2l, lnw, lnb, out, 1);
}

// round 11
// speedup vs baseline: 1.2477x; 1.2477x over previous
#include <cuda_runtime.h>
#include <cuda_fp16.h>
#include <cstdint>

#define N_NODES 50000
#define N_EDGES 800000
#define DIM 128
#define LN_EPS 1e-5f
#define SCAN_B 196          // ceil(50000/256)
#define WTILE 16384         // floats per 128x128 weight

// ---------------- scratch: __device__ globals, device-side references only --
__device__ int    g_is64;
__device__ int    g_deg[N_NODES];
__device__ int    g_rowptr[N_NODES + 1];
__device__ int    g_cursor[N_NODES];
__device__ int    g_colsrc[N_EDGES];
__device__ int    g_bsum[256];
__device__ float4 g_X4[(size_t)N_NODES * 32];      // tf32-rounded input x
__device__ float4 g_W4[4 * WTILE / 4];             // tf32-rounded weights
__device__ __half g_P16[(size_t)N_NODES * DIM];    // mean branch (pre-agg), fp16
__device__ float4 g_Q4[(size_t)N_NODES * 32];      // self branch, fp32
__device__ float4 g_h14[(size_t)N_NODES * 32];     // layer-1 out (tf32-rounded)

__device__ __forceinline__ float to_tf32(float v) {
    uint32_t u;
    asm("cvt.rna.tf32.f32 %0, %1;" : "=r"(u) : "f"(v));
    return __uint_as_float(u);
}

// ---------------- setup: zero deg + dtype probe + tf32 pre-round ------------
__global__ void k_setup(const float* __restrict__ x,
                        const float* __restrict__ W1l, const float* __restrict__ W1r,
                        const float* __restrict__ W2l, const float* __restrict__ W2r,
                        const int* __restrict__ ei32) {
    int i = blockIdx.x * blockDim.x + threadIdx.x;
    if (i < N_NODES * DIM) ((float*)g_X4)[i] = to_tf32(x[i]);
    if (i < WTILE) {
        float* W = (float*)g_W4;
        W[i]             = to_tf32(W1l[i]);
        W[WTILE + i]     = to_tf32(W1r[i]);
        W[2 * WTILE + i] = to_tf32(W2l[i]);
        W[3 * WTILE + i] = to_tf32(W2r[i]);
    }
    if (i < N_NODES) g_deg[i] = 0;
    if (i == 0) {
        int allzero = 1;
        for (int k = 0; k < 64; k++)
            if (ei32[2 * k + 1] != 0) { allzero = 0; break; }
        g_is64 = allzero;
    }
}

__device__ __forceinline__ int edge_at(const void* __restrict__ ei, int pos) {
    if (g_is64) return (int)((const long long*)ei)[pos];
    return ((const int*)ei)[pos];
}

// ---------------- CSR build ----------------
__global__ void k_hist(const void* __restrict__ ei) {
    int e = blockIdx.x * blockDim.x + threadIdx.x;
    if (e < N_EDGES) {
        int d = edge_at(ei, N_EDGES + e);
        if (d >= 0 && d < N_NODES) atomicAdd(&g_deg[d], 1);
    }
}

__global__ void k_scan1() {                       // grid=196: per-block sums
    __shared__ int sm[256];
    int t = threadIdx.x;
    int i = blockIdx.x * 256 + t;
    sm[t] = (i < N_NODES) ? g_deg[i] : 0;
    __syncthreads();
#pragma unroll
    for (int off = 128; off > 0; off >>= 1) {
        if (t < off) sm[t] += sm[t + off];
        __syncthreads();
    }
    if (t == 0) g_bsum[blockIdx.x] = sm[0];
}

// merged scan2+scan3: each block redundantly scans the 196 block sums,
// then does its local exclusive scan and writes rowptr/cursor.
__global__ void k_scan3() {                       // grid=196
    __shared__ int smb[256];
    __shared__ int sml[256];
    int t = threadIdx.x;
    // scan block sums
    int bv = (t < SCAN_B) ? g_bsum[t] : 0;
    smb[t] = bv;
    __syncthreads();
#pragma unroll
    for (int off = 1; off < 256; off <<= 1) {
        int u = (t >= off) ? smb[t - off] : 0;
        __syncthreads();
        smb[t] += u;
        __syncthreads();
    }
    int block_off = (blockIdx.x == 0) ? 0 : smb[blockIdx.x - 1];
    // local scan
    int i = blockIdx.x * 256 + t;
    int v = (i < N_NODES) ? g_deg[i] : 0;
    sml[t] = v;
    __syncthreads();
#pragma unroll
    for (int off = 1; off < 256; off <<= 1) {
        int u = (t >= off) ? sml[t - off] : 0;
        __syncthreads();
        sml[t] += u;
        __syncthreads();
    }
    int excl = sml[t] - v + block_off;
    if (i < N_NODES) { g_rowptr[i] = excl; g_cursor[i] = excl; }
    if (i == N_NODES - 1) g_rowptr[N_NODES] = excl + v;
}

__global__ void k_fill(const void* __restrict__ ei) {
    int e = blockIdx.x * blockDim.x + threadIdx.x;
    if (e < N_EDGES) {
        int d = edge_at(ei, N_EDGES + e);
        if (d >= 0 && d < N_NODES) {
            int s = edge_at(ei, e);
            if (s < 0) s = 0;
            if (s >= N_NODES) s = N_NODES - 1;
            int pos = atomicAdd(&g_cursor[d], 1);
            g_colsrc[pos] = s;
        }
    }
}

// ---------------- tf32 GEMM (R9 tile shape + 2-stage cp.async pipeline) -----
// out = A @ W^T. A [N,128] tf32-pre-rounded; W [128,128] tf32-pre-rounded.
// Block 128x128, 8 warps x (32x64), occupancy 2, stride-36 smem (conflict-free).
__device__ __forceinline__ void mma_tf32(float c[4], const uint32_t a[4],
                                         const uint32_t b[2]) {
    asm volatile(
        "mma.sync.aligned.m16n8k8.row.col.f32.tf32.tf32.f32 "
        "{%0,%1,%2,%3}, {%4,%5,%6,%7}, {%8,%9}, {%0,%1,%2,%3};\n"
        : "+f"(c[0]), "+f"(c[1]), "+f"(c[2]), "+f"(c[3])
        : "r"(a[0]), "r"(a[1]), "r"(a[2]), "r"(a[3]),
          "r"(b[0]), "r"(b[1]));
}

__device__ __forceinline__ void cp_async16(float* smem_dst, const float* gsrc, bool valid) {
    uint32_t s = (uint32_t)__cvta_generic_to_shared(smem_dst);
    int sz = valid ? 16 : 0;
    asm volatile("cp.async.ca.shared.global [%0], [%1], 16, %2;\n"
                 :: "r"(s), "l"(gsrc), "r"(sz));
}
#define CP_COMMIT() asm volatile("cp.async.commit_group;\n")
#define CP_WAIT1()  asm volatile("cp.async.wait_group 1;\n")
#define CP_WAIT0()  asm volatile("cp.async.wait_group 0;\n")

#define SPAD 36
#define STG_F (128 * SPAD)                       // floats per (A or B) stage
#define GEMM_SMEM_BYTES (4 * STG_F * 4)          // A0,A1,B0,B1 = 73728 B

__global__ __launch_bounds__(256, 2) void k_gemm(int layer1, int widx, int out_fp16) {
    extern __shared__ float dynsm[];
    const float* A = layer1 ? (const float*)g_X4 : (const float*)g_h14;
    const float* W = (const float*)g_W4 + (size_t)widx * WTILE;

    int tid = threadIdx.x;
    int r0 = blockIdx.x * 128;

    // stage fill: 128 rows x 32 k for A and B each; 4 cp.async16 per array/thread
#define FILL_STAGE(stg, ka)                                                    \
    {                                                                          \
        float* Ab = dynsm + (stg) * STG_F;                                     \
        float* Bb = dynsm + 2 * STG_F + (stg) * STG_F;                         \
        _Pragma("unroll")                                                      \
        for (int i = 0; i < 4; i++) {                                          \
            int linear = i * 256 + tid;                                        \
            int m = linear >> 3;                                               \
            int kv = (linear & 7) * 4;                                         \
            int row = r0 + m;                                                  \
            cp_async16(&Ab[m * SPAD + kv],                                     \
                       A + (size_t)row * DIM + (ka) + kv, row < N_NODES);      \
            cp_async16(&Bb[m * SPAD + kv],                                     \
                       W + m * DIM + (ka) + kv, true);                         \
        }                                                                      \
        CP_COMMIT();                                                           \
    }

    FILL_STAGE(0, 0)

    int wid = tid >> 5, lane = tid & 31;
    int g = lane >> 2, tg = lane & 3;
    int warp_m = (wid >> 1) * 32;
    int warp_n = (wid & 1) * 64;

    float acc[2][8][4];
#pragma unroll
    for (int mt = 0; mt < 2; mt++)
#pragma unroll
        for (int nt = 0; nt < 8; nt++)
#pragma unroll
            for (int q = 0; q < 4; q++) acc[mt][nt][q] = 0.f;

#pragma unroll 1
    for (int kt = 0; kt < 4; kt++) {
        if (kt < 3) {
            FILL_STAGE((kt + 1) & 1, (kt + 1) * 32)
            CP_WAIT1();
        } else {
            CP_WAIT0();
        }
        __syncthreads();

        const float* Ab = dynsm + (kt & 1) * STG_F;
        const float* Bb = dynsm + 2 * STG_F + (kt & 1) * STG_F;
#pragma unroll
        for (int ks = 0; ks < 32; ks += 8) {
            int kc = ks + tg;
            uint32_t afr[2][4];
#pragma unroll
            for (int mt = 0; mt < 2; mt++) {
                const float* Ar = Ab + (warp_m + mt * 16 + g) * SPAD;
                afr[mt][0] = __float_as_uint(Ar[kc]);
                afr[mt][1] = __float_as_uint(Ar[8 * SPAD + kc]);
                afr[mt][2] = __float_as_uint(Ar[kc + 4]);
                afr[mt][3] = __float_as_uint(Ar[8 * SPAD + kc + 4]);
            }
#pragma unroll
            for (int nt = 0; nt < 8; nt++) {
                const float* Br = Bb + (warp_n + nt * 8 + g) * SPAD;
                uint32_t bfr[2] = { __float_as_uint(Br[kc]),
                                    __float_as_uint(Br[kc + 4]) };
                mma_tf32(acc[0][nt], afr[0], bfr);
                mma_tf32(acc[1][nt], afr[1], bfr);
            }
        }
        __syncthreads();
    }

    // epilogue: c0:(g,2tg) c1:(g,2tg+1) c2:(g+8,2tg) c3:(g+8,2tg+1)
    float* Q = (float*)g_Q4;
#pragma unroll
    for (int mt = 0; mt < 2; mt++) {
        int row0 = r0 + warp_m + mt * 16 + g;
#pragma unroll
        for (int nt = 0; nt < 8; nt++) {
            int col = warp_n + nt * 8 + tg * 2;
            if (out_fp16) {
                if (row0 < N_NODES)
                    *(__half2*)(g_P16 + (size_t)row0 * DIM + col) =
                        __floats2half2_rn(acc[mt][nt][0], acc[mt][nt][1]);
                if (row0 + 8 < N_NODES)
                    *(__half2*)(g_P16 + (size_t)(row0 + 8) * DIM + col) =
                        __floats2half2_rn(acc[mt][nt][2], acc[mt][nt][3]);
            } else {
                if (row0 < N_NODES)
                    *(float2*)(Q + (size_t)row0 * DIM + col) =
                        make_float2(acc[mt][nt][0], acc[mt][nt][1]);
                if (row0 + 8 < N_NODES)
                    *(float2*)(Q + (size_t)(row0 + 8) * DIM + col) =
                        make_float2(acc[mt][nt][2], acc[mt][nt][3]);
            }
        }
    }
}

// ---------------- combine: out = [LN]( relu( mean_gather(P16) + Q + bias ) ) -
#define GATHER1(sidx)                                                          \
    {                                                                          \
        uint2 u = *(const uint2*)(g_P16 + (size_t)(sidx) * DIM + lane * 4);    \
        float2 fa = __half22float2(*(__half2*)&u.x);                           \
        float2 fb = __half22float2(*(__half2*)&u.y);                           \
        ax += fa.x; ay += fa.y; az += fb.x; aw += fb.y;                        \
    }

__global__ void k_combine(const float* __restrict__ bias,
                          const float* __restrict__ lnw,
                          const float* __restrict__ lnb,
                          float* __restrict__ out_ext, int do_ln)
{
    int w = (blockIdx.x * blockDim.x + threadIdx.x) >> 5;
    int lane = threadIdx.x & 31;
    if (w >= N_NODES) return;
    int beg = g_rowptr[w];
    int end = g_rowptr[w + 1];

    float ax = 0.f, ay = 0.f, az = 0.f, aw = 0.f;
    for (int base = beg; base < end; base += 32) {
        int rem = end - base;
        if (rem > 32) rem = 32;
        int idx = g_colsrc[base + (lane < rem ? lane : 0)];
        int j = 0;
        for (; j + 8 <= rem; j += 8) {
            int s0 = __shfl_sync(0xFFFFFFFFu, idx, j);
            int s1 = __shfl_sync(0xFFFFFFFFu, idx, j + 1);
            int s2 = __shfl_sync(0xFFFFFFFFu, idx, j + 2);
            int s3 = __shfl_sync(0xFFFFFFFFu, idx, j + 3);
            int s4 = __shfl_sync(0xFFFFFFFFu, idx, j + 4);
            int s5 = __shfl_sync(0xFFFFFFFFu, idx, j + 5);
            int s6 = __shfl_sync(0xFFFFFFFFu, idx, j + 6);
            int s7 = __shfl_sync(0xFFFFFFFFu, idx, j + 7);
            GATHER1(s0) GATHER1(s1) GATHER1(s2) GATHER1(s3)
            GATHER1(s4) GATHER1(s5) GATHER1(s6) GATHER1(s7)
        }
        for (; j < rem; j++) {
            int s = __shfl_sync(0xFFFFFFFFu, idx, j);
            GATHER1(s)
        }
    }
    int cnt = end - beg;
    float inv = 1.f / (float)(cnt > 0 ? cnt : 1);

    float4 q = g_Q4[(size_t)w * 32 + lane];
    float4 b4 = ((const float4*)bias)[lane];
    float vx = fmaxf(ax * inv + q.x + b4.x, 0.f);
    float vy = fmaxf(ay * inv + q.y + b4.y, 0.f);
    float vz = fmaxf(az * inv + q.z + b4.z, 0.f);
    float vw = fmaxf(aw * inv + q.w + b4.w, 0.f);

    if (!do_ln) {
        g_h14[(size_t)w * 32 + lane] =
            make_float4(to_tf32(vx), to_tf32(vy), to_tf32(vz), to_tf32(vw));
        return;
    }
    float s = (vx + vy) + (vz + vw);
#pragma unroll
    for (int off = 16; off > 0; off >>= 1)
        s += __shfl_xor_sync(0xFFFFFFFFu, s, off);
    float mu = s * (1.f / 128.f);
    float dx = vx - mu, dy = vy - mu, dz = vz - mu, dw = vw - mu;
    float sq = (dx * dx + dy * dy) + (dz * dz + dw * dw);
#pragma unroll
    for (int off = 16; off > 0; off >>= 1)
        sq += __shfl_xor_sync(0xFFFFFFFFu, sq, off);
    float rs = rsqrtf(sq * (1.f / 128.f) + LN_EPS);
    float4 wv = ((const float4*)lnw)[lane];
    float4 bv = ((const float4*)lnb)[lane];
    float4 o;
    o.x = dx * rs * wv.x + bv.x;
    o.y = dy * rs * wv.y + bv.y;
    o.z = dz * rs * wv.z + bv.z;
    o.w = dw * rs * wv.w + bv.w;
    ((float4*)out_ext)[(size_t)w * 32 + lane] = o;
}

// ---------------- launch ----------------
extern "C" void kernel_launch(void* const* d_in, const int* in_sizes, int n_in,
                              void* d_out, int out_size) {
    const float* x   = (const float*)d_in[0];
    const void*  ei  = d_in[1];
    const float* W1l = (const float*)d_in[2];
    const float* b1l = (const float*)d_in[3];
    const float* W1r = (const float*)d_in[4];
    const float* W2l = (const float*)d_in[5];
    const float* b2l = (const float*)d_in[6];
    const float* W2r = (const float*)d_in[7];
    const float* lnw = (const float*)d_in[8];
    const float* lnb = (const float*)d_in[9];
    float* out = (float*)d_out;

    const int TB = 256;
    int gridS  = (N_NODES * DIM + TB - 1) / TB;  // covers rounding + zero + probe
    int gridE  = (N_EDGES + TB - 1) / TB;
    int gridWN = (N_NODES * 32 + TB - 1) / TB;
    int gridG  = (N_NODES + 127) / 128;          // 391

    cudaFuncSetAttribute(k_gemm, cudaFuncAttributeMaxDynamicSharedMemorySize,
                         GEMM_SMEM_BYTES);

    // setup: tf32 rounding + zero deg + dtype probe (root of both chains)
    k_setup<<<gridS, TB>>>(x, W1l, W1r, W2l, W2r, (const int*)ei);

    // try to fork the CSR chain onto a second stream (overlaps with GEMM1)
    cudaStream_t s2 = 0;
    cudaEvent_t ev_fork = 0, ev_csr = 0;
    bool forked =
        (cudaStreamCreateWithFlags(&s2, cudaStreamNonBlocking) == cudaSuccess) &&
        (cudaEventCreateWithFlags(&ev_fork, cudaEventDisableTiming) == cudaSuccess) &&
        (cudaEventCreateWithFlags(&ev_csr, cudaEventDisableTiming) == cudaSuccess);

    cudaStream_t sc = forked ? s2 : (cudaStream_t)0;
    if (forked) {
        cudaEventRecord(ev_fork, 0);
        cudaStreamWaitEvent(s2, ev_fork, 0);
    }
    k_hist<<<gridE, TB, 0, sc>>>(ei);
    k_scan1<<<SCAN_B, 256, 0, sc>>>();
    k_scan3<<<SCAN_B, 256, 0, sc>>>();
    k_fill<<<gridE, TB, 0, sc>>>(ei);
    if (forked) cudaEventRecord(ev_csr, s2);

    // layer 1 GEMMs on the main stream (concurrent with CSR build)
    k_gemm<<<gridG, TB, GEMM_SMEM_BYTES>>>(1, 0, 1);   // P16 = x @ W1l^T
    k_gemm<<<gridG, TB, GEMM_SMEM_BYTES>>>(1, 1, 0);   // Q   = x @ W1r^T

    if (forked) cudaStreamWaitEvent(0, ev_csr, 0);     // join CSR before combine
    k_combine<<<gridWN, TB>>>(b1l, lnw, lnb, out, 0);  // -> g_h14 (tf32-rounded)

    // layer 2
    k_gemm<<<gridG, TB, GEMM_SMEM_BYTES>>>(0, 2, 1);   // P16 = h1 @ W2l^T
    k_gemm<<<gridG, TB, GEMM_SMEM_BYTES>>>(0, 3, 0);   // Q   = h1 @ W2r^T
    k_combine<<<gridWN, TB>>>(b2l, lnw, lnb, out, 1);  // + LN -> out
}